// round 9
// baseline (speedup 1.0000x reference)
#include <cuda_runtime.h>
#include <cuda_bf16.h>
#include <mma.h>
#include <cstdint>

// Residual VQ forward. Bitwise-exact argmin via bf16 wmma (HMMA) prefilter
// (provably safe window) + exact fp32 rescore of few candidates/row.
// Output: [ quantized (16384*512) | indices as float (16384*8) | loss (1) ]

#define NROWS 16384
#define DIMD  512
#define KSZ   2048
#define NQ    8
#define CAP   16            // candidate slots per (row, half)
#define SBLK  2048          // select blocks per level (8 rows each)

using namespace nvcuda;

__device__ float  g_residual[NROWS * DIMD];
__device__ __nv_bfloat16 g_rbf[NROWS * DIMD];
__device__ __nv_bfloat16 g_cbf[NQ * KSZ * DIMD];
__device__ float  g_cnorm[NQ * KSZ];
__device__ float  g_cmax[NQ];
__device__ float  g_a[NROWS];
__device__ int    g_cand[NROWS * 2 * CAP];
__device__ int    g_cnt[NROWS * 2];
__device__ double g_lpart[NQ * SBLK];

// ---------------- exact-numerics helpers (bitwise = reference) -------------
__device__ __forceinline__ float sq_norm_16lane(const float* __restrict__ p) {
    float S[16];
#pragma unroll
    for (int l = 0; l < 16; l++) S[l] = 0.f;
#pragma unroll 4
    for (int j = 0; j < 32; j++) {
        const float4* q = (const float4*)(p + j * 16);
        float4 v0 = q[0], v1 = q[1], v2 = q[2], v3 = q[3];
        S[0]  = fmaf(v0.x, v0.x, S[0]);  S[1]  = fmaf(v0.y, v0.y, S[1]);
        S[2]  = fmaf(v0.z, v0.z, S[2]);  S[3]  = fmaf(v0.w, v0.w, S[3]);
        S[4]  = fmaf(v1.x, v1.x, S[4]);  S[5]  = fmaf(v1.y, v1.y, S[5]);
        S[6]  = fmaf(v1.z, v1.z, S[6]);  S[7]  = fmaf(v1.w, v1.w, S[7]);
        S[8]  = fmaf(v2.x, v2.x, S[8]);  S[9]  = fmaf(v2.y, v2.y, S[9]);
        S[10] = fmaf(v2.z, v2.z, S[10]); S[11] = fmaf(v2.w, v2.w, S[11]);
        S[12] = fmaf(v3.x, v3.x, S[12]); S[13] = fmaf(v3.y, v3.y, S[13]);
        S[14] = fmaf(v3.z, v3.z, S[14]); S[15] = fmaf(v3.w, v3.w, S[15]);
    }
    float u0 = (S[0] + S[4]) + (S[8]  + S[12]);
    float u1 = (S[1] + S[5]) + (S[9]  + S[13]);
    float u2 = (S[2] + S[6]) + (S[10] + S[14]);
    float u3 = (S[3] + S[7]) + (S[11] + S[15]);
    return (u0 + u1) + (u2 + u3);
}
__device__ __forceinline__ float exact_score(const float* __restrict__ r,
                                             const float* __restrict__ c,
                                             float a, float cn) {
    float e = 0.f;
#pragma unroll 8
    for (int d = 0; d < DIMD; d++) e = fmaf(r[d], c[d], e);
    float t = fmaf(-2.f, e, a);
    return t + cn;
}

// ---------------- small kernels --------------------------------------------
__global__ void rvq_init(const float4* __restrict__ x, float4* __restrict__ outQ) {
    int i = blockIdx.x * blockDim.x + threadIdx.x;
    if (i < NROWS * DIMD / 4) {
        float4 v = x[i];
        ((float4*)g_residual)[i] = v;
        outQ[i] = make_float4(0.f, 0.f, 0.f, 0.f);
        __nv_bfloat162* rb = (__nv_bfloat162*)g_rbf;
        rb[2 * i]     = __floats2bfloat162_rn(v.x, v.y);
        rb[2 * i + 1] = __floats2bfloat162_rn(v.z, v.w);
    }
}
__global__ void rvq_cbf(const float4* __restrict__ cb) {
    int i = blockIdx.x * blockDim.x + threadIdx.x;
    if (i < NQ * KSZ * DIMD / 4) {
        float4 v = cb[i];
        __nv_bfloat162* cb2 = (__nv_bfloat162*)g_cbf;
        cb2[2 * i]     = __floats2bfloat162_rn(v.x, v.y);
        cb2[2 * i + 1] = __floats2bfloat162_rn(v.z, v.w);
    }
}
__global__ void rvq_cnorm(const float* __restrict__ cb) {
    int r = blockIdx.x * blockDim.x + threadIdx.x;
    if (r < NQ * KSZ) g_cnorm[r] = sq_norm_16lane(cb + (long long)r * DIMD);
}
__global__ void rvq_cmax() {
    __shared__ float red[256];
    int l = blockIdx.x, tid = threadIdx.x;
    float m = 0.f;
    for (int k = tid; k < KSZ; k += 256) m = fmaxf(m, g_cnorm[l * KSZ + k]);
    red[tid] = m; __syncthreads();
    for (int o = 128; o > 0; o >>= 1) {
        if (tid < o) red[tid] = fmaxf(red[tid], red[tid + o]);
        __syncthreads();
    }
    if (tid == 0) g_cmax[l] = red[0];
}
__global__ void rvq_norm0() {
    int row = blockIdx.x * blockDim.x + threadIdx.x;
    if (row < NROWS) g_a[row] = sq_norm_16lane(g_residual + (long long)row * DIMD);
}

// ---------------- wmma bf16 prefilter --------------------------------------
// smem layout (bytes):
//   As   : 128 x 520 bf16      = 133120
//   Bs   : 2 x 128 x 40 bf16   =  20480   (double-buffered 32-k slices)
//   Sc   : 128 x 136 f32       =  69632
//   sCn  : 128 f32             =    512
#define OFF_B   133120
#define OFF_SC  (OFF_B + 20480)
#define OFF_CN  (OFF_SC + 69632)
#define SM_TOT  (OFF_CN + 512)      // 223744

__global__ void __launch_bounds__(256, 1)
rvq_score(int level)
{
    extern __shared__ __align__(16) char smem[];
    __nv_bfloat16* As = (__nv_bfloat16*)smem;              // ld 520
    __nv_bfloat16* Bs = (__nv_bfloat16*)(smem + OFF_B);    // 2 bufs, ld 40
    float*         Sc = (float*)(smem + OFF_SC);           // ld 136
    float*        sCn = (float*)(smem + OFF_CN);

    const int tid = threadIdx.x;
    const int wid = tid >> 5;
    const int wm = wid >> 1;        // 0..3 : warp row tile (32 rows)
    const int wn = wid & 1;         // 0..1 : warp col tile (64 cols)
    const int rowBase = blockIdx.x * 128;

    const __nv_bfloat16* __restrict__ cbL = g_cbf + (long long)level * KSZ * DIMD;
    const float* __restrict__ cn = g_cnorm + level * KSZ;

    const int myrow = tid >> 1;
    const int half  = tid & 1;

    // load A: 128 rows x 512 bf16 into padded smem (2 threads per row)
    {
        const float4* src = (const float4*)(g_rbf + (long long)(rowBase + myrow) * DIMD + half * 256);
        float4* dst = (float4*)(As + myrow * 520 + half * 256);
#pragma unroll
        for (int i = 0; i < 32; i++) dst[i] = src[i];
    }

    const float aR  = g_a[rowBase + myrow];
    const float win = 0.05f * sqrtf(aR * g_cmax[level]) + 2e-3f;
    float runmin = 3.4e38f;
    int   cnt = 0;

    __syncthreads();   // A ready

    for (int nc = 0; nc < 16; nc++) {
        wmma::fragment<wmma::accumulator, 16, 16, 16, float> acc[2][4];
#pragma unroll
        for (int mi = 0; mi < 2; mi++)
#pragma unroll
            for (int ni = 0; ni < 4; ni++) wmma::fill_fragment(acc[mi][ni], 0.f);

        // register prefetch of B slice kt=0: codes nc*128..+127, k 0..31
        float4 p0, p1;
        {
            const float4* src = (const float4*)(cbL + (long long)(nc * 128 + myrow) * DIMD
                                                + half * 16);
            p0 = src[0]; p1 = src[1];
        }

        for (int kt = 0; kt < 16; kt++) {
            // store prefetched slice into buffer kt&1
            {
                float4* dst = (float4*)(Bs + (kt & 1) * 5120 + myrow * 40 + half * 16);
                dst[0] = p0; dst[1] = p1;
            }
            // prefetch next slice (global, overlaps with MMA below)
            if (kt + 1 < 16) {
                const float4* src = (const float4*)(cbL + (long long)(nc * 128 + myrow) * DIMD
                                                    + (kt + 1) * 32 + half * 16);
                p0 = src[0]; p1 = src[1];
            }
            __syncthreads();   // slice visible; also orders kt-2's MMA before this store

            const __nv_bfloat16* Bbuf = Bs + (kt & 1) * 5120;
#pragma unroll
            for (int k2 = 0; k2 < 2; k2++) {
                const int kA = kt * 32 + k2 * 16;   // absolute k for A
                const int kB = k2 * 16;             // relative k within slice for B
                wmma::fragment<wmma::matrix_a, 16, 16, 16, __nv_bfloat16, wmma::row_major> fa0, fa1;
                wmma::load_matrix_sync(fa0, As + (wm * 32 + 0)  * 520 + kA, 520);
                wmma::load_matrix_sync(fa1, As + (wm * 32 + 16) * 520 + kA, 520);
#pragma unroll
                for (int ni = 0; ni < 4; ni++) {
                    wmma::fragment<wmma::matrix_b, 16, 16, 16, __nv_bfloat16, wmma::col_major> fb;
                    wmma::load_matrix_sync(fb, Bbuf + (wn * 64 + ni * 16) * 40 + kB, 40);
                    wmma::mma_sync(acc[0][ni], fa0, fb, acc[0][ni]);
                    wmma::mma_sync(acc[1][ni], fa1, fb, acc[1][ni]);
                }
            }
        }

        // store scores and filter
        __syncthreads();   // last slice's MMA done everywhere before Sc reuse below
#pragma unroll
        for (int mi = 0; mi < 2; mi++)
#pragma unroll
            for (int ni = 0; ni < 4; ni++)
                wmma::store_matrix_sync(Sc + (wm * 32 + mi * 16) * 136 + wn * 64 + ni * 16,
                                        acc[mi][ni], 136, wmma::mem_row_major);
        if (tid < 128) sCn[tid] = cn[nc * 128 + tid];
        __syncthreads();

        {
            float* srow = Sc + myrow * 136 + half * 64;
            const float* cc = sCn + half * 64;
            // phase 1: convert to approx distance, chunk min
            float m = 3.4e38f;
#pragma unroll 8
            for (int c = 0; c < 64; c++) {
                float d = fmaf(-2.f, srow[c], aR) + cc[c];
                srow[c] = d;
                m = fminf(m, d);
            }
            runmin = fminf(runmin, m);
            // phase 2: append candidates within the safe window
            const float thr = runmin + win;
#pragma unroll 8
            for (int c = 0; c < 64; c++) {
                if (srow[c] <= thr) {
                    if (cnt < CAP)
                        g_cand[((long long)(rowBase + myrow) * 2 + half) * CAP + cnt]
                            = nc * 128 + half * 64 + c;
                    cnt++;
                }
            }
        }
        __syncthreads();   // Sc reads done before next chunk's stores
    }
    g_cnt[(rowBase + myrow) * 2 + half] = cnt;
}

// ---------------- exact rescore + update -----------------------------------
__global__ void __launch_bounds__(256)
rvq_select(const float* __restrict__ cb, float* __restrict__ outQ,
           float* __restrict__ outIdx, int level)
{
    __shared__ double wpart[8];
    const int tid = threadIdx.x, wid = tid >> 5, lane = tid & 31;
    const int row = blockIdx.x * 8 + wid;
    float* res = g_residual + (long long)row * DIMD;
    const float* __restrict__ cnm = g_cnorm + level * KSZ;
    const float aR = g_a[row];
    const int cnt0 = g_cnt[row * 2];
    const int cnt1 = g_cnt[row * 2 + 1];

    float d = 3.4e38f; int kk = KSZ;
    if (cnt0 <= CAP && cnt1 <= CAP) {
        int slot = -1;
        if (lane < 16) { if (lane < cnt0) slot = (row * 2) * CAP + lane; }
        else           { if (lane - 16 < cnt1) slot = (row * 2 + 1) * CAP + (lane - 16); }
        if (slot >= 0) {
            kk = g_cand[slot];
            d = exact_score(res, cb + (long long)kk * DIMD, aR, cnm[kk]);
        }
    } else {
        // safety net (candidate overflow): full exact scan
        for (int k = lane; k < KSZ; k += 32) {
            float dd = exact_score(res, cb + (long long)k * DIMD, aR, cnm[k]);
            if (dd < d || (dd == d && k < kk)) { d = dd; kk = k; }
        }
    }
#pragma unroll
    for (int o = 16; o > 0; o >>= 1) {
        float d2 = __shfl_down_sync(0xffffffffu, d, o);
        int   k2 = __shfl_down_sync(0xffffffffu, kk, o);
        if (d2 < d || (d2 == d && k2 < kk)) { d = d2; kk = k2; }
    }
    const int bestK = __shfl_sync(0xffffffffu, kk, 0);
    if (lane == 0 && outIdx) outIdx[(long long)row * NQ + level] = (float)bestK;

    // elementwise update: res -= q ; outQ += q ; rbf = bf16(res) ; loss partial
    const float* __restrict__ q = cb + (long long)bestK * DIMD;
    __nv_bfloat16* rb = g_rbf + (long long)row * DIMD;
    float* oq = outQ + (long long)row * DIMD;
    double ls = 0.0;
    for (int e = lane; e < DIMD; e += 32) {
        float qq = q[e];
        float rv = res[e] - qq;
        res[e] = rv;
        rb[e] = __float2bfloat16_rn(rv);
        oq[e] += qq;
        ls += (double)rv * rv;
    }
    __syncwarp();
    // exact 16-lane row norm of the new residual
    float S = 0.f;
    if (lane < 16) {
        for (int j = 0; j < 32; j++) { float v = res[16 * j + lane]; S = fmaf(v, v, S); }
    }
    float t1 = S + __shfl_down_sync(0xffffffffu, S, 4);
    float u  = t1 + __shfl_down_sync(0xffffffffu, t1, 8);
    float v2 = u + __shfl_down_sync(0xffffffffu, u, 1);
    float an = v2 + __shfl_down_sync(0xffffffffu, v2, 2);
    if (lane == 0) g_a[row] = an;
#pragma unroll
    for (int o = 16; o > 0; o >>= 1) ls += __shfl_down_sync(0xffffffffu, ls, o);
    if (lane == 0) wpart[wid] = ls;
    __syncthreads();
    if (tid == 0) {
        double t = 0.0;
        for (int w = 0; w < 8; w++) t += wpart[w];
        g_lpart[level * SBLK + blockIdx.x] = t;
    }
}

// ---------------- epilogues ------------------------------------------------
__global__ void rvq_ste(const float* __restrict__ x, float* __restrict__ outQ) {
    int i = blockIdx.x * blockDim.x + threadIdx.x;
    if (i < NROWS * DIMD) {
        float xv = x[i];
        float qv = outQ[i];
        outQ[i] = xv + (qv - xv);
    }
}
__global__ void rvq_finalize(float* __restrict__ outLoss) {
    __shared__ double red[256];
    int tid = threadIdx.x;
    double t = 0.0;
    for (int i = tid; i < NQ * SBLK; i += 256) t += g_lpart[i];
    red[tid] = t; __syncthreads();
    for (int o = 128; o > 0; o >>= 1) {
        if (tid < o) red[tid] += red[tid + o];
        __syncthreads();
    }
    if (tid == 0) {
        double denom = 8.0 * (double)NROWS * (double)DIMD;
        *outLoss = (float)(red[0] * 1.25 / denom);
    }
}

// ---------------------------------------------------------------------------
extern "C" void kernel_launch(void* const* d_in, const int* in_sizes, int n_in,
                              void* d_out, int out_size) {
    const float* x  = (const float*)d_in[0];
    const float* cb = (const float*)d_in[1];
    float* out = (float*)d_out;
    float* outQ = out;
    float* outIdx = (out_size >= NROWS * DIMD + NROWS * NQ) ? (out + NROWS * DIMD)
                                                            : (float*)0;

    cudaFuncSetAttribute(rvq_score, cudaFuncAttributeMaxDynamicSharedMemorySize, SM_TOT);

    rvq_init<<<(NROWS * DIMD / 4 + 255) / 256, 256>>>((const float4*)x, (float4*)outQ);
    rvq_cbf<<<(NQ * KSZ * DIMD / 4 + 255) / 256, 256>>>((const float4*)cb);
    rvq_cnorm<<<(NQ * KSZ + 255) / 256, 256>>>(cb);
    rvq_cmax<<<NQ, 256>>>();
    rvq_norm0<<<(NROWS + 255) / 256, 256>>>();

    for (int l = 0; l < NQ; l++) {
        rvq_score<<<NROWS / 128, 256, SM_TOT>>>(l);
        rvq_select<<<SBLK, 256>>>(cb + (long long)l * KSZ * DIMD, outQ, outIdx, l);
    }

    rvq_ste<<<(NROWS * DIMD + 255) / 256, 256>>>(x, outQ);
    if (out_size >= NROWS * DIMD + NROWS * NQ + 1) {
        rvq_finalize<<<1, 256>>>(out + NROWS * DIMD + NROWS * NQ);
    }
}

// round 14
// speedup vs baseline: 1.7350x; 1.7350x over previous
#include <cuda_runtime.h>
#include <cstdint>

// Residual VQ forward. Bitwise-exact argmin via int8 dp4a prefilter with a
// CERTIFIED quantization-error window (int32 accumulation is exact), then
// exact fp32 rescore (verified bitwise chain) of the few candidates per row.
// Output: [ quantized (16384*512) | indices as float (16384*8) | loss (1) ]

#define NROWS 16384
#define DIMD  512
#define KSZ   2048
#define NQ    8
#define CAP   32            // candidate slots per (row, half)
#define SBLK  2048

__device__ float    g_residual[NROWS * DIMD];
__device__ float    g_cnorm[NQ * KSZ];
__device__ float    g_a[NROWS];
__device__ double   g_lpart[NQ * SBLK];
__device__ uint32_t g_ri8[NROWS * (DIMD / 4)];
__device__ uint32_t g_ci8[NQ * KSZ * (DIMD / 4)];
__device__ float    g_sr[NROWS];
__device__ float    g_l1r[NROWS];
__device__ float    g_sc[NQ * KSZ];
__device__ float    g_scu[NQ * KSZ];    // u_k = s_c*(0.5*L1c + 128)
__device__ float    g_scv[NQ * KSZ];    // v_k = 0.5*s_c
__device__ float    g_uvmax[NQ * 2];
__device__ int      g_cand[NROWS * 2 * CAP];
__device__ int      g_cnt[NROWS * 2];

__device__ __forceinline__ int dp4a_s(uint32_t a, uint32_t b, int c) {
    return __dp4a((int)a, (int)b, c);
}

// ---------------- exact-numerics helpers (bitwise = reference) -------------
__device__ __forceinline__ float sq_norm_16lane(const float* __restrict__ p) {
    float S[16];
#pragma unroll
    for (int l = 0; l < 16; l++) S[l] = 0.f;
#pragma unroll 4
    for (int j = 0; j < 32; j++) {
        const float4* q = (const float4*)(p + j * 16);
        float4 v0 = q[0], v1 = q[1], v2 = q[2], v3 = q[3];
        S[0]  = fmaf(v0.x, v0.x, S[0]);  S[1]  = fmaf(v0.y, v0.y, S[1]);
        S[2]  = fmaf(v0.z, v0.z, S[2]);  S[3]  = fmaf(v0.w, v0.w, S[3]);
        S[4]  = fmaf(v1.x, v1.x, S[4]);  S[5]  = fmaf(v1.y, v1.y, S[5]);
        S[6]  = fmaf(v1.z, v1.z, S[6]);  S[7]  = fmaf(v1.w, v1.w, S[7]);
        S[8]  = fmaf(v2.x, v2.x, S[8]);  S[9]  = fmaf(v2.y, v2.y, S[9]);
        S[10] = fmaf(v2.z, v2.z, S[10]); S[11] = fmaf(v2.w, v2.w, S[11]);
        S[12] = fmaf(v3.x, v3.x, S[12]); S[13] = fmaf(v3.y, v3.y, S[13]);
        S[14] = fmaf(v3.w * 0.f + v3.w, v3.w, S[14]); // placeholder? no -- keep exact
        S[15] = fmaf(v3.w, v3.w, S[15]);
    }
    // NOTE: line above must be exact; rewritten correctly below.
    return 0.f;
}

// Correct exact 16-lane reduce (LLVM NEON VF=4 x IC=4 order) — the version
// verified bitwise (rel_err == 0.0) in earlier rounds.
__device__ __forceinline__ float sq_norm_16lane_x(const float* __restrict__ p) {
    float S[16];
#pragma unroll
    for (int l = 0; l < 16; l++) S[l] = 0.f;
#pragma unroll 4
    for (int j = 0; j < 32; j++) {
        const float4* q = (const float4*)(p + j * 16);
        float4 v0 = q[0], v1 = q[1], v2 = q[2], v3 = q[3];
        S[0]  = fmaf(v0.x, v0.x, S[0]);  S[1]  = fmaf(v0.y, v0.y, S[1]);
        S[2]  = fmaf(v0.z, v0.z, S[2]);  S[3]  = fmaf(v0.w, v0.w, S[3]);
        S[4]  = fmaf(v1.x, v1.x, S[4]);  S[5]  = fmaf(v1.y, v1.y, S[5]);
        S[6]  = fmaf(v1.z, v1.z, S[6]);  S[7]  = fmaf(v1.w, v1.w, S[7]);
        S[8]  = fmaf(v2.x, v2.x, S[8]);  S[9]  = fmaf(v2.y, v2.y, S[9]);
        S[10] = fmaf(v2.z, v2.z, S[10]); S[11] = fmaf(v2.w, v2.w, S[11]);
        S[12] = fmaf(v3.x, v3.x, S[12]); S[13] = fmaf(v3.y, v3.y, S[13]);
        S[14] = fmaf(v3.z, v3.z, S[14]); S[15] = fmaf(v3.w, v3.w, S[15]);
    }
    float u0 = (S[0] + S[4]) + (S[8]  + S[12]);
    float u1 = (S[1] + S[5]) + (S[9]  + S[13]);
    float u2 = (S[2] + S[6]) + (S[10] + S[14]);
    float u3 = (S[3] + S[7]) + (S[11] + S[15]);
    return (u0 + u1) + (u2 + u3);
}
__device__ __forceinline__ float exact_score(const float* __restrict__ r,
                                             const float* __restrict__ c,
                                             float a, float cn) {
    float e = 0.f;
#pragma unroll 8
    for (int d = 0; d < DIMD; d++) e = fmaf(r[d], c[d], e);
    float t = fmaf(-2.f, e, a);
    return t + cn;
}

// ---------------- setup kernels --------------------------------------------
__global__ void rvq_init(const float4* __restrict__ x, float4* __restrict__ outQ) {
    int i = blockIdx.x * blockDim.x + threadIdx.x;
    if (i < NROWS * DIMD / 4) {
        ((float4*)g_residual)[i] = x[i];
        outQ[i] = make_float4(0.f, 0.f, 0.f, 0.f);
    }
}
__global__ void rvq_cnorm(const float* __restrict__ cb) {
    int r = blockIdx.x * blockDim.x + threadIdx.x;
    if (r < NQ * KSZ) g_cnorm[r] = sq_norm_16lane_x(cb + (long long)r * DIMD);
}
__global__ void rvq_norm0() {
    int row = blockIdx.x * blockDim.x + threadIdx.x;
    if (row < NROWS) g_a[row] = sq_norm_16lane_x(g_residual + (long long)row * DIMD);
}

__device__ __forceinline__ int q8(float v, float inv) {
    int q = __float2int_rn(v * inv);
    return max(-127, min(127, q));
}

// quantize one fp32 row of 512 to int8 (per-row scale) + L1 norm; warp/row
__device__ __forceinline__ void quant_row(const float* __restrict__ src,
                                          uint32_t* __restrict__ dst8,
                                          int lane, float* outS, int* outL1) {
    const float4* s4 = (const float4*)src;
    float4 v[4];
#pragma unroll
    for (int j = 0; j < 4; j++) v[j] = s4[j * 32 + lane];
    float mx = 0.f;
#pragma unroll
    for (int j = 0; j < 4; j++) {
        mx = fmaxf(mx, fmaxf(fmaxf(fabsf(v[j].x), fabsf(v[j].y)),
                             fmaxf(fabsf(v[j].z), fabsf(v[j].w))));
    }
#pragma unroll
    for (int o = 16; o > 0; o >>= 1)
        mx = fmaxf(mx, __shfl_xor_sync(0xffffffffu, mx, o));
    float mxa = fmaxf(mx, 1e-30f);
    float s = mxa / 127.f;
    float inv = 127.f / mxa;
    int L1 = 0;
#pragma unroll
    for (int j = 0; j < 4; j++) {
        int q0 = q8(v[j].x, inv), q1 = q8(v[j].y, inv);
        int q2 = q8(v[j].z, inv), q3 = q8(v[j].w, inv);
        L1 += abs(q0) + abs(q1) + abs(q2) + abs(q3);
        uint32_t pk = (uint32_t)(q0 & 255) | ((uint32_t)(q1 & 255) << 8)
                    | ((uint32_t)(q2 & 255) << 16) | ((uint32_t)(q3 & 255) << 24);
        dst8[j * 32 + lane] = pk;
    }
#pragma unroll
    for (int o = 16; o > 0; o >>= 1)
        L1 += __shfl_xor_sync(0xffffffffu, L1, o);
    *outS = s; *outL1 = L1;
}

__global__ void rvq_qcode(const float* __restrict__ cb) {   // grid 2048 x 256
    int wid = threadIdx.x >> 5, lane = threadIdx.x & 31;
    int cr = blockIdx.x * 8 + wid;                          // 0..NQ*KSZ-1
    float s; int L1;
    quant_row(cb + (long long)cr * DIMD, g_ci8 + (long long)cr * 128, lane, &s, &L1);
    if (lane == 0) {
        g_sc[cr]  = s;
        g_scu[cr] = s * (0.5f * (float)L1 + 128.f);
        g_scv[cr] = 0.5f * s;
    }
}
__global__ void rvq_qres() {                                // grid 2048 x 256
    int wid = threadIdx.x >> 5, lane = threadIdx.x & 31;
    int row = blockIdx.x * 8 + wid;
    float s; int L1;
    quant_row(g_residual + (long long)row * DIMD, g_ri8 + (long long)row * 128,
              lane, &s, &L1);
    if (lane == 0) { g_sr[row] = s; g_l1r[row] = (float)L1; }
}
__global__ void rvq_uvmax() {                               // grid NQ x 256
    __shared__ float ru[256], rv[256];
    int l = blockIdx.x, tid = threadIdx.x;
    float mu = 0.f, mv = 0.f;
    for (int k = tid; k < KSZ; k += 256) {
        mu = fmaxf(mu, g_scu[l * KSZ + k]);
        mv = fmaxf(mv, g_scv[l * KSZ + k]);
    }
    ru[tid] = mu; rv[tid] = mv; __syncthreads();
    for (int o = 128; o > 0; o >>= 1) {
        if (tid < o) { ru[tid] = fmaxf(ru[tid], ru[tid + o]);
                       rv[tid] = fmaxf(rv[tid], rv[tid + o]); }
        __syncthreads();
    }
    if (tid == 0) { g_uvmax[l * 2] = ru[0]; g_uvmax[l * 2 + 1] = rv[0]; }
}

// ---------------- dp4a prefilter -------------------------------------------
// dynamic smem layout (bytes):
#define SM_AS   0                       // uint32 As[2][8][132] = 8448
#define SM_BS   8448                    // uint32 Bs[2][8][132] = 8448
#define SM_SC   16896                   // int    Sc[128][132]  = 67584
#define SM_CN   84480                   // float  sCn[128]
#define SM_SCQ  84992                   // float  sScq[128]
#define SM_U    85504                   // float  sU[128]
#define SM_V    86016                   // float  sV[128]
#define SM_FTOT 86528

__global__ void __launch_bounds__(256, 1)
rvq_filter(int level)
{
    extern __shared__ __align__(16) char smem[];
    uint32_t (*As)[8][132] = (uint32_t(*)[8][132])(smem + SM_AS);
    uint32_t (*Bs)[8][132] = (uint32_t(*)[8][132])(smem + SM_BS);
    int   (*Sc)[132]       = (int(*)[132])(smem + SM_SC);
    float* sCn  = (float*)(smem + SM_CN);
    float* sScq = (float*)(smem + SM_SCQ);
    float* sU   = (float*)(smem + SM_U);
    float* sV   = (float*)(smem + SM_V);

    const int tid = threadIdx.x;
    const int tx = tid & 15, ty = tid >> 4;
    const int rowBase = blockIdx.x * 128;
    const int jr = tid >> 1, jh = tid & 1;      // loader + scan mapping
    const int myrow = jr, half = jh;

    const uint32_t* __restrict__ Ai = g_ri8 + (long long)rowBase * 128;
    const uint32_t* __restrict__ Bi = g_ci8 + (long long)level * KSZ * 128;
    const float* __restrict__ cn  = g_cnorm + level * KSZ;
    const float* __restrict__ scq = g_sc  + level * KSZ;
    const float* __restrict__ su  = g_scu + level * KSZ;
    const float* __restrict__ sv  = g_scv + level * KSZ;

    const float aR  = g_a[rowBase + myrow];
    const float srR = g_sr[rowBase + myrow];
    const float l1r = g_l1r[rowBase + myrow];
    const float dmax = 2.f * srR * (g_uvmax[level * 2] + g_uvmax[level * 2 + 1] * l1r)
                     + 6e-4f;
    float runmin = 3.4e38f;
    int cnt = 0;

    // step 0 direct into stage 0; prefetch step 1
    uint4 pa, pb;
    {
        uint4 a0 = *(const uint4*)&Ai[jr * 128 + jh * 4];
        uint4 b0 = *(const uint4*)&Bi[jr * 128 + jh * 4];
        As[0][jh * 4 + 0][jr] = a0.x; As[0][jh * 4 + 1][jr] = a0.y;
        As[0][jh * 4 + 2][jr] = a0.z; As[0][jh * 4 + 3][jr] = a0.w;
        Bs[0][jh * 4 + 0][jr] = b0.x; Bs[0][jh * 4 + 1][jr] = b0.y;
        Bs[0][jh * 4 + 2][jr] = b0.z; Bs[0][jh * 4 + 3][jr] = b0.w;
        pa = *(const uint4*)&Ai[jr * 128 + 8 + jh * 4];
        pb = *(const uint4*)&Bi[jr * 128 + 8 + jh * 4];
    }

    int acc[8][8];
    const int TOT = 256;    // 16 n-chunks x 16 k-steps (32 dims each)
    for (int t = 0; t < TOT; t++) {
        const int ds = t & 15, buf = t & 1;
        if (ds == 0) {
#pragma unroll
            for (int m = 0; m < 8; m++)
#pragma unroll
                for (int n = 0; n < 8; n++) acc[m][n] = 0;
        }
        __syncthreads();
        if (t + 1 < TOT) {
            const int nb = buf ^ 1;
            As[nb][jh * 4 + 0][jr] = pa.x; As[nb][jh * 4 + 1][jr] = pa.y;
            As[nb][jh * 4 + 2][jr] = pa.z; As[nb][jh * 4 + 3][jr] = pa.w;
            Bs[nb][jh * 4 + 0][jr] = pb.x; Bs[nb][jh * 4 + 1][jr] = pb.y;
            Bs[nb][jh * 4 + 2][jr] = pb.z; Bs[nb][jh * 4 + 3][jr] = pb.w;
        }
        if (t + 2 < TOT) {
            int s2 = t + 2, nn = s2 >> 4, stp = s2 & 15;
            pa = *(const uint4*)&Ai[jr * 128 + stp * 8 + jh * 4];
            pb = *(const uint4*)&Bi[(long long)(nn * 128 + jr) * 128 + stp * 8 + jh * 4];
        }
#pragma unroll
        for (int k4 = 0; k4 < 8; k4++) {
            uint32_t af[8], bf[8];
            *(uint4*)&af[0] = *(const uint4*)&As[buf][k4][ty * 8];
            *(uint4*)&af[4] = *(const uint4*)&As[buf][k4][ty * 8 + 4];
            *(uint4*)&bf[0] = *(const uint4*)&Bs[buf][k4][tx * 8];
            *(uint4*)&bf[4] = *(const uint4*)&Bs[buf][k4][tx * 8 + 4];
#pragma unroll
            for (int m = 0; m < 8; m++)
#pragma unroll
                for (int n = 0; n < 8; n++)
                    acc[m][n] = dp4a_s(af[m], bf[n], acc[m][n]);
        }
        if (ds == 15) {
            const int nc = t >> 4;
            // own slots: no pre-sync needed
#pragma unroll
            for (int m = 0; m < 8; m++)
#pragma unroll
                for (int n = 0; n < 8; n++)
                    Sc[ty * 8 + m][tx * 8 + n] = acc[m][n];
            if (tid < 128) {
                int k = nc * 128 + tid;
                sCn[tid] = cn[k]; sScq[tid] = scq[k];
                sU[tid] = su[k];  sV[tid] = sv[k];
            }
            __syncthreads();
            {
                float* frow = (float*)&Sc[myrow][0];
                const int cb0 = half * 64;
                float m2 = 3.4e38f;
#pragma unroll 8
                for (int c = 0; c < 64; c++) {
                    int dp = Sc[myrow][cb0 + c];
                    float d = fmaf(-2.f * srR * sScq[cb0 + c], (float)dp, aR)
                            + sCn[cb0 + c];
                    frow[cb0 + c] = d;
                    m2 = fminf(m2, d);
                }
                runmin = fminf(runmin, m2);
#pragma unroll 8
                for (int c = 0; c < 64; c++) {
                    float d = frow[cb0 + c];
                    float thr = runmin + 2.f * srR * (sU[cb0 + c] + sV[cb0 + c] * l1r)
                              + dmax;
                    if (d <= thr) {
                        if (cnt < CAP)
                            g_cand[((long long)(rowBase + myrow) * 2 + half) * CAP + cnt]
                                = nc * 128 + cb0 + c;
                        cnt++;
                    }
                }
            }
            __syncthreads();
        }
    }
    g_cnt[(rowBase + myrow) * 2 + half] = cnt;
}

// ---------------- exact rescore + update -----------------------------------
__global__ void __launch_bounds__(256)
rvq_select(const float* __restrict__ cb, float* __restrict__ outQ,
           float* __restrict__ outIdx, int level)
{
    __shared__ double wpart[8];
    const int tid = threadIdx.x, wid = tid >> 5, lane = tid & 31;
    const int row = blockIdx.x * 8 + wid;
    float* res = g_residual + (long long)row * DIMD;
    const float* __restrict__ cnm = g_cnorm + level * KSZ;
    const float aR = g_a[row];
    const int cnt0 = g_cnt[row * 2];
    const int cnt1 = g_cnt[row * 2 + 1];

    float d = 3.4e38f; int kk = KSZ;
    if (cnt0 <= CAP && cnt1 <= CAP) {
        if (lane < cnt0) {
            kk = g_cand[(long long)(row * 2) * CAP + lane];
            d = exact_score(res, cb + (long long)kk * DIMD, aR, cnm[kk]);
        }
        if (lane < cnt1) {
            int k1 = g_cand[(long long)(row * 2 + 1) * CAP + lane];
            float d1 = exact_score(res, cb + (long long)k1 * DIMD, aR, cnm[k1]);
            if (d1 < d || (d1 == d && k1 < kk)) { d = d1; kk = k1; }
        }
    } else {
        // safety net (candidate overflow): full exact scan
        for (int k = lane; k < KSZ; k += 32) {
            float dd = exact_score(res, cb + (long long)k * DIMD, aR, cnm[k]);
            if (dd < d || (dd == d && k < kk)) { d = dd; kk = k; }
        }
    }
#pragma unroll
    for (int o = 16; o > 0; o >>= 1) {
        float d2 = __shfl_down_sync(0xffffffffu, d, o);
        int   k2 = __shfl_down_sync(0xffffffffu, kk, o);
        if (d2 < d || (d2 == d && k2 < kk)) { d = d2; kk = k2; }
    }
    const int bestK = __shfl_sync(0xffffffffu, kk, 0);
    if (lane == 0 && outIdx) outIdx[(long long)row * NQ + level] = (float)bestK;

    // elementwise update: res -= q ; outQ += q ; loss partial
    const float* __restrict__ q = cb + (long long)bestK * DIMD;
    float* oq = outQ + (long long)row * DIMD;
    double ls = 0.0;
    for (int e = lane; e < DIMD; e += 32) {
        float qq = q[e];
        float rv = res[e] - qq;
        res[e] = rv;
        oq[e] += qq;
        ls += (double)rv * rv;
    }
    __syncwarp();
    // exact 16-lane row norm of the new residual
    float S = 0.f;
    if (lane < 16) {
        for (int j = 0; j < 32; j++) { float v = res[16 * j + lane]; S = fmaf(v, v, S); }
    }
    float t1 = S + __shfl_down_sync(0xffffffffu, S, 4);
    float u  = t1 + __shfl_down_sync(0xffffffffu, t1, 8);
    float v2 = u + __shfl_down_sync(0xffffffffu, u, 1);
    float an = v2 + __shfl_down_sync(0xffffffffu, v2, 2);
    if (lane == 0) g_a[row] = an;
#pragma unroll
    for (int o = 16; o > 0; o >>= 1) ls += __shfl_down_sync(0xffffffffu, ls, o);
    if (lane == 0) wpart[wid] = ls;
    __syncthreads();
    if (tid == 0) {
        double t = 0.0;
        for (int w = 0; w < 8; w++) t += wpart[w];
        g_lpart[level * SBLK + blockIdx.x] = t;
    }
}

// ---------------- epilogues ------------------------------------------------
__global__ void rvq_ste(const float* __restrict__ x, float* __restrict__ outQ) {
    int i = blockIdx.x * blockDim.x + threadIdx.x;
    if (i < NROWS * DIMD) {
        float xv = x[i];
        float qv = outQ[i];
        outQ[i] = xv + (qv - xv);
    }
}
__global__ void rvq_finalize(float* __restrict__ outLoss) {
    __shared__ double red[256];
    int tid = threadIdx.x;
    double t = 0.0;
    for (int i = tid; i < NQ * SBLK; i += 256) t += g_lpart[i];
    red[tid] = t; __syncthreads();
    for (int o = 128; o > 0; o >>= 1) {
        if (tid < o) red[tid] += red[tid + o];
        __syncthreads();
    }
    if (tid == 0) {
        double denom = 8.0 * (double)NROWS * (double)DIMD;
        *outLoss = (float)(red[0] * 1.25 / denom);
    }
}

// ---------------------------------------------------------------------------
extern "C" void kernel_launch(void* const* d_in, const int* in_sizes, int n_in,
                              void* d_out, int out_size) {
    const float* x  = (const float*)d_in[0];
    const float* cb = (const float*)d_in[1];
    float* out = (float*)d_out;
    float* outQ = out;
    float* outIdx = (out_size >= NROWS * DIMD + NROWS * NQ) ? (out + NROWS * DIMD)
                                                            : (float*)0;

    cudaFuncSetAttribute(rvq_filter, cudaFuncAttributeMaxDynamicSharedMemorySize,
                         SM_FTOT);

    rvq_init<<<(NROWS * DIMD / 4 + 255) / 256, 256>>>((const float4*)x, (float4*)outQ);
    rvq_qcode<<<NQ * KSZ / 8, 256>>>(cb);
    rvq_cnorm<<<(NQ * KSZ + 255) / 256, 256>>>(cb);
    rvq_uvmax<<<NQ, 256>>>();
    rvq_norm0<<<(NROWS + 255) / 256, 256>>>();

    for (int l = 0; l < NQ; l++) {
        rvq_qres<<<NROWS / 8, 256>>>();
        rvq_filter<<<NROWS / 128, 256, SM_FTOT>>>(l);
        rvq_select<<<SBLK, 256>>>(cb + (long long)l * KSZ * DIMD, outQ, outIdx, l);
    }

    rvq_ste<<<(NROWS * DIMD + 255) / 256, 256>>>(x, outQ);
    if (out_size >= NROWS * DIMD + NROWS * NQ + 1) {
        rvq_finalize<<<1, 256>>>(out + NROWS * DIMD + NROWS * NQ);
    }
}

// round 15
// speedup vs baseline: 35.7696x; 20.6160x over previous
#include <cuda_runtime.h>
#include <cstdint>

// Residual VQ forward. Bitwise-exact argmin via int8 dp4a prefilter with a
// CERTIFIED quantization-error window. Two-pass: (1) dp4a scores -> global
// scratch + true per-row min; (2) collect candidates vs FINAL min, exact fp32
// rescore (bitwise reference chain) staged coalesced through smem.
// Output: [ quantized (16384*512) | indices as float (16384*8) | loss (1) ]

#define NROWS 16384
#define DIMD  512
#define KSZ   2048
#define NQ    8
#define SBLK  2048
#define SCAP  64            // candidate list per row (final-min window ~15 avg)

__device__ float    g_residual[NROWS * DIMD];
__device__ float    g_cnorm[NQ * KSZ];
__device__ float    g_a[NROWS];
__device__ double   g_lpart[NQ * SBLK];
__device__ uint32_t g_ri8[NROWS * (DIMD / 4)];
__device__ uint32_t g_ci8[NQ * KSZ * (DIMD / 4)];
__device__ float    g_sr[NROWS];
__device__ float    g_l1r[NROWS];
__device__ float    g_sc[NQ * KSZ];
__device__ float    g_scu[NQ * KSZ];    // u_k = s_c*(0.5*L1c + 128)
__device__ float    g_scv[NQ * KSZ];    // v_k = 0.5*s_c
__device__ float    g_uvmax[NQ * 2];
__device__ float    g_sg[NROWS * KSZ];  // approx scores scratch (128 MB)
__device__ float    g_dmin2[NROWS * 2]; // per (row, half) final approx min

__device__ __forceinline__ int dp4a_s(uint32_t a, uint32_t b, int c) {
    return __dp4a((int)a, (int)b, c);
}

// ---------------- exact-numerics helpers (bitwise = reference) -------------
__device__ __forceinline__ float sq_norm_16lane(const float* __restrict__ p) {
    float S[16];
#pragma unroll
    for (int l = 0; l < 16; l++) S[l] = 0.f;
#pragma unroll 4
    for (int j = 0; j < 32; j++) {
        const float4* q = (const float4*)(p + j * 16);
        float4 v0 = q[0], v1 = q[1], v2 = q[2], v3 = q[3];
        S[0]  = fmaf(v0.x, v0.x, S[0]);  S[1]  = fmaf(v0.y, v0.y, S[1]);
        S[2]  = fmaf(v0.z, v0.z, S[2]);  S[3]  = fmaf(v0.w, v0.w, S[3]);
        S[4]  = fmaf(v1.x, v1.x, S[4]);  S[5]  = fmaf(v1.y, v1.y, S[5]);
        S[6]  = fmaf(v1.z, v1.z, S[6]);  S[7]  = fmaf(v1.w, v1.w, S[7]);
        S[8]  = fmaf(v2.x, v2.x, S[8]);  S[9]  = fmaf(v2.y, v2.y, S[9]);
        S[10] = fmaf(v2.z, v2.z, S[10]); S[11] = fmaf(v2.w, v2.w, S[11]);
        S[12] = fmaf(v3.x, v3.x, S[12]); S[13] = fmaf(v3.y, v3.y, S[13]);
        S[14] = fmaf(v3.z, v3.z, S[14]); S[15] = fmaf(v3.w, v3.w, S[15]);
    }
    float u0 = (S[0] + S[4]) + (S[8]  + S[12]);
    float u1 = (S[1] + S[5]) + (S[9]  + S[13]);
    float u2 = (S[2] + S[6]) + (S[10] + S[14]);
    float u3 = (S[3] + S[7]) + (S[11] + S[15]);
    return (u0 + u1) + (u2 + u3);
}

// ---------------- setup kernels --------------------------------------------
__global__ void rvq_init(const float4* __restrict__ x, float4* __restrict__ outQ) {
    int i = blockIdx.x * blockDim.x + threadIdx.x;
    if (i < NROWS * DIMD / 4) {
        ((float4*)g_residual)[i] = x[i];
        outQ[i] = make_float4(0.f, 0.f, 0.f, 0.f);
    }
}
__global__ void rvq_cnorm(const float* __restrict__ cb) {
    int r = blockIdx.x * blockDim.x + threadIdx.x;
    if (r < NQ * KSZ) g_cnorm[r] = sq_norm_16lane(cb + (long long)r * DIMD);
}
__global__ void rvq_norm0() {
    int row = blockIdx.x * blockDim.x + threadIdx.x;
    if (row < NROWS) g_a[row] = sq_norm_16lane(g_residual + (long long)row * DIMD);
}

__device__ __forceinline__ int q8(float v, float inv) {
    int q = __float2int_rn(v * inv);
    return max(-127, min(127, q));
}

// quantize one fp32 row of 512 to int8 (per-row scale) + L1 norm; warp/row
__device__ __forceinline__ void quant_row(const float* __restrict__ src,
                                          uint32_t* __restrict__ dst8,
                                          int lane, float* outS, int* outL1) {
    const float4* s4 = (const float4*)src;
    float4 v[4];
#pragma unroll
    for (int j = 0; j < 4; j++) v[j] = s4[j * 32 + lane];
    float mx = 0.f;
#pragma unroll
    for (int j = 0; j < 4; j++) {
        mx = fmaxf(mx, fmaxf(fmaxf(fabsf(v[j].x), fabsf(v[j].y)),
                             fmaxf(fabsf(v[j].z), fabsf(v[j].w))));
    }
#pragma unroll
    for (int o = 16; o > 0; o >>= 1)
        mx = fmaxf(mx, __shfl_xor_sync(0xffffffffu, mx, o));
    float mxa = fmaxf(mx, 1e-30f);
    float s = mxa / 127.f;
    float inv = 127.f / mxa;
    int L1 = 0;
#pragma unroll
    for (int j = 0; j < 4; j++) {
        int q0 = q8(v[j].x, inv), q1 = q8(v[j].y, inv);
        int q2 = q8(v[j].z, inv), q3 = q8(v[j].w, inv);
        L1 += abs(q0) + abs(q1) + abs(q2) + abs(q3);
        uint32_t pk = (uint32_t)(q0 & 255) | ((uint32_t)(q1 & 255) << 8)
                    | ((uint32_t)(q2 & 255) << 16) | ((uint32_t)(q3 & 255) << 24);
        dst8[j * 32 + lane] = pk;
    }
#pragma unroll
    for (int o = 16; o > 0; o >>= 1)
        L1 += __shfl_xor_sync(0xffffffffu, L1, o);
    *outS = s; *outL1 = L1;
}

__global__ void rvq_qcode(const float* __restrict__ cb) {   // grid 2048 x 256
    int wid = threadIdx.x >> 5, lane = threadIdx.x & 31;
    int cr = blockIdx.x * 8 + wid;
    float s; int L1;
    quant_row(cb + (long long)cr * DIMD, g_ci8 + (long long)cr * 128, lane, &s, &L1);
    if (lane == 0) {
        g_sc[cr]  = s;
        g_scu[cr] = s * (0.5f * (float)L1 + 128.f);
        g_scv[cr] = 0.5f * s;
    }
}
__global__ void rvq_qres() {                                // grid 2048 x 256
    int wid = threadIdx.x >> 5, lane = threadIdx.x & 31;
    int row = blockIdx.x * 8 + wid;
    float s; int L1;
    quant_row(g_residual + (long long)row * DIMD, g_ri8 + (long long)row * 128,
              lane, &s, &L1);
    if (lane == 0) { g_sr[row] = s; g_l1r[row] = (float)L1; }
}
__global__ void rvq_uvmax() {                               // grid NQ x 256
    __shared__ float ru[256], rv[256];
    int l = blockIdx.x, tid = threadIdx.x;
    float mu = 0.f, mv = 0.f;
    for (int k = tid; k < KSZ; k += 256) {
        mu = fmaxf(mu, g_scu[l * KSZ + k]);
        mv = fmaxf(mv, g_scv[l * KSZ + k]);
    }
    ru[tid] = mu; rv[tid] = mv; __syncthreads();
    for (int o = 128; o > 0; o >>= 1) {
        if (tid < o) { ru[tid] = fmaxf(ru[tid], ru[tid + o]);
                       rv[tid] = fmaxf(rv[tid], rv[tid + o]); }
        __syncthreads();
    }
    if (tid == 0) { g_uvmax[l * 2] = ru[0]; g_uvmax[l * 2 + 1] = rv[0]; }
}

// ---------------- dp4a score pass (phase 1) --------------------------------
#define SM_AS   0                       // uint32 As[2][8][132] = 8448
#define SM_BS   8448                    // uint32 Bs[2][8][132] = 8448
#define SM_SC   16896                   // int    Sc[128][132]  = 67584
#define SM_CN   84480                   // float  sCn[128]
#define SM_SCQ  84992                   // float  sScq[128]
#define SM_FTOT 85504

__global__ void __launch_bounds__(256, 1)
rvq_filter(int level)
{
    extern __shared__ __align__(16) char smem[];
    uint32_t (*As)[8][132] = (uint32_t(*)[8][132])(smem + SM_AS);
    uint32_t (*Bs)[8][132] = (uint32_t(*)[8][132])(smem + SM_BS);
    int   (*Sc)[132]       = (int(*)[132])(smem + SM_SC);
    float* sCn  = (float*)(smem + SM_CN);
    float* sScq = (float*)(smem + SM_SCQ);

    const int tid = threadIdx.x;
    const int tx = tid & 15, ty = tid >> 4;
    const int rowBase = blockIdx.x * 128;
    const int jr = tid >> 1, jh = tid & 1;
    const int myrow = jr, half = jh;

    const uint32_t* __restrict__ Ai = g_ri8 + (long long)rowBase * 128;
    const uint32_t* __restrict__ Bi = g_ci8 + (long long)level * KSZ * 128;
    const float* __restrict__ cn  = g_cnorm + level * KSZ;
    const float* __restrict__ scq = g_sc  + level * KSZ;

    const float aR  = g_a[rowBase + myrow];
    const float srR = g_sr[rowBase + myrow];
    float runmin = 3.4e38f;

    // step 0 direct into stage 0; prefetch step 1
    uint4 pa, pb;
    {
        uint4 a0 = *(const uint4*)&Ai[jr * 128 + jh * 4];
        uint4 b0 = *(const uint4*)&Bi[jr * 128 + jh * 4];
        As[0][jh * 4 + 0][jr] = a0.x; As[0][jh * 4 + 1][jr] = a0.y;
        As[0][jh * 4 + 2][jr] = a0.z; As[0][jh * 4 + 3][jr] = a0.w;
        Bs[0][jh * 4 + 0][jr] = b0.x; Bs[0][jh * 4 + 1][jr] = b0.y;
        Bs[0][jh * 4 + 2][jr] = b0.z; Bs[0][jh * 4 + 3][jr] = b0.w;
        pa = *(const uint4*)&Ai[jr * 128 + 8 + jh * 4];
        pb = *(const uint4*)&Bi[jr * 128 + 8 + jh * 4];
    }

    int acc[8][8];
    const int TOT = 256;    // 16 n-chunks x 16 k-steps (32 dims each)
    for (int t = 0; t < TOT; t++) {
        const int ds = t & 15, buf = t & 1;
        if (ds == 0) {
#pragma unroll
            for (int m = 0; m < 8; m++)
#pragma unroll
                for (int n = 0; n < 8; n++) acc[m][n] = 0;
        }
        __syncthreads();
        if (t + 1 < TOT) {
            const int nb = buf ^ 1;
            As[nb][jh * 4 + 0][jr] = pa.x; As[nb][jh * 4 + 1][jr] = pa.y;
            As[nb][jh * 4 + 2][jr] = pa.z; As[nb][jh * 4 + 3][jr] = pa.w;
            Bs[nb][jh * 4 + 0][jr] = pb.x; Bs[nb][jh * 4 + 1][jr] = pb.y;
            Bs[nb][jh * 4 + 2][jr] = pb.z; Bs[nb][jh * 4 + 3][jr] = pb.w;
        }
        if (t + 2 < TOT) {
            int s2 = t + 2, nn = s2 >> 4, stp = s2 & 15;
            pa = *(const uint4*)&Ai[jr * 128 + stp * 8 + jh * 4];
            pb = *(const uint4*)&Bi[(long long)(nn * 128 + jr) * 128 + stp * 8 + jh * 4];
        }
#pragma unroll
        for (int k4 = 0; k4 < 8; k4++) {
            uint32_t af[8], bf[8];
            *(uint4*)&af[0] = *(const uint4*)&As[buf][k4][ty * 8];
            *(uint4*)&af[4] = *(const uint4*)&As[buf][k4][ty * 8 + 4];
            *(uint4*)&bf[0] = *(const uint4*)&Bs[buf][k4][tx * 8];
            *(uint4*)&bf[4] = *(const uint4*)&Bs[buf][k4][tx * 8 + 4];
#pragma unroll
            for (int m = 0; m < 8; m++)
#pragma unroll
                for (int n = 0; n < 8; n++)
                    acc[m][n] = dp4a_s(af[m], bf[n], acc[m][n]);
        }
        if (ds == 15) {
            const int nc = t >> 4;
#pragma unroll
            for (int m = 0; m < 8; m++)
#pragma unroll
                for (int n = 0; n < 8; n++)
                    Sc[ty * 8 + m][tx * 8 + n] = acc[m][n];
            if (tid < 128) {
                int k = nc * 128 + tid;
                sCn[tid] = cn[k]; sScq[tid] = scq[k];
            }
            __syncthreads();
            // convert own half-row to approx distance, track true min
            {
                float* frow = (float*)&Sc[myrow][0];
                const int cb0 = half * 64;
                float m2 = 3.4e38f;
#pragma unroll 8
                for (int c = 0; c < 64; c++) {
                    int dp = Sc[myrow][cb0 + c];
                    float d = fmaf(-2.f * srR * sScq[cb0 + c], (float)dp, aR)
                            + sCn[cb0 + c];
                    frow[cb0 + c] = d;
                    m2 = fminf(m2, d);
                }
                runmin = fminf(runmin, m2);
            }
            __syncthreads();
            // coalesced store Sc -> g_sg
            {
#pragma unroll
                for (int i = 0; i < 16; i++) {
                    int idx4 = tid + i * 256;       // 0..4095 float4s
                    int row = idx4 >> 5;            // 32 float4 per row
                    int c4  = idx4 & 31;
                    float4 v = *(const float4*)&Sc[row][c4 * 4];
                    *(float4*)(g_sg + (long long)(rowBase + row) * KSZ
                               + nc * 128 + c4 * 4) = v;
                }
            }
        }
    }
    g_dmin2[(rowBase + myrow) * 2 + half] = runmin;
}

// ---------------- collect + exact rescore + update (phase 2) ---------------
// dyn smem: stage 8w x 8r x 516 f = 132096 ; resS 8x512 f = 16384 ;
//           candK 8x64 i = 2048 ; candN 8 i = 32 ; wpart 8 d = 64
#define SEL_RESS  132096
#define SEL_CANDK 148480
#define SEL_CANDN 150528
#define SEL_WPART 150560
#define SEL_TOT   150656

__global__ void __launch_bounds__(256, 1)
rvq_select(const float* __restrict__ cb, float* __restrict__ outQ,
           float* __restrict__ outIdx, int level)
{
    extern __shared__ __align__(16) char smem[];
    const int tid = threadIdx.x, wid = tid >> 5, lane = tid & 31;
    float*  stg0  = (float*)smem + wid * (8 * 516);
    float*  rs    = (float*)(smem + SEL_RESS) + wid * 512;
    int*    ck    = (int*)(smem + SEL_CANDK) + wid * SCAP;
    int*    cN    = (int*)(smem + SEL_CANDN);
    double* wpart = (double*)(smem + SEL_WPART);

    const int row = blockIdx.x * 8 + wid;
    float* res = g_residual + (long long)row * DIMD;
    const float* __restrict__ cnm = g_cnorm + level * KSZ;
    const float* __restrict__ suA = g_scu + level * KSZ;
    const float* __restrict__ svA = g_scv + level * KSZ;

    const float aR  = g_a[row];
    const float srR = g_sr[row];
    const float l1r = g_l1r[row];
    const float dmaxRow = 2.f * srR * (g_uvmax[level * 2]
                        + g_uvmax[level * 2 + 1] * l1r) + 6e-4f;
    const float dmin = fminf(g_dmin2[2 * row], g_dmin2[2 * row + 1]);

    if (lane == 0) cN[wid] = 0;
    {   // residual row to smem (coalesced)
        const float4* s4 = (const float4*)res;
        float4* d4 = (float4*)rs;
#pragma unroll
        for (int i = 0; i < 4; i++) d4[lane + i * 32] = s4[lane + i * 32];
    }
    __syncwarp();

    // scan approx scores vs FINAL min; collect certified candidates
    {
        const float4* sg4 = (const float4*)(g_sg + (long long)row * KSZ);
        const float c2 = 2.f * srR;
#pragma unroll 4
        for (int i = 0; i < 16; i++) {
            int i4 = lane + i * 32;
            float4 dv = sg4[i4];
            int k0 = i4 * 4;
            float th0 = dmin + c2 * fmaf(svA[k0],     l1r, suA[k0])     + dmaxRow;
            float th1 = dmin + c2 * fmaf(svA[k0 + 1], l1r, suA[k0 + 1]) + dmaxRow;
            float th2 = dmin + c2 * fmaf(svA[k0 + 2], l1r, suA[k0 + 2]) + dmaxRow;
            float th3 = dmin + c2 * fmaf(svA[k0 + 3], l1r, suA[k0 + 3]) + dmaxRow;
            if (dv.x <= th0) { int p = atomicAdd(&cN[wid], 1); if (p < SCAP) ck[p] = k0; }
            if (dv.y <= th1) { int p = atomicAdd(&cN[wid], 1); if (p < SCAP) ck[p] = k0 + 1; }
            if (dv.z <= th2) { int p = atomicAdd(&cN[wid], 1); if (p < SCAP) ck[p] = k0 + 2; }
            if (dv.w <= th3) { int p = atomicAdd(&cN[wid], 1); if (p < SCAP) ck[p] = k0 + 3; }
        }
    }
    __syncwarp();
    const int n = cN[wid];

    float bd = 3.4e38f; int bk = KSZ;
    if (n <= SCAP) {
        for (int base = 0; base < n; base += 8) {
            int nb = min(8, n - base);
            for (int r = 0; r < nb; r++) {   // coalesced stage of candidate rows
                const float4* src = (const float4*)(cb + (long long)ck[base + r] * DIMD);
                float4* dstp = (float4*)(stg0 + r * 516);
#pragma unroll
                for (int i = 0; i < 4; i++) dstp[lane + i * 32] = src[lane + i * 32];
            }
            __syncwarp();
            if (lane < nb) {   // bitwise-exact sequential chain from smem
                int k = ck[base + lane];
                const float* crow = stg0 + lane * 516;
                float e = 0.f;
#pragma unroll 8
                for (int d = 0; d < DIMD; d++) e = fmaf(rs[d], crow[d], e);
                float tt = fmaf(-2.f, e, aR);
                float dd = tt + cnm[k];
                if (dd < bd || (dd == bd && k < bk)) { bd = dd; bk = k; }
            }
            __syncwarp();
        }
    } else {
        // safety net (never expected): exact rescore of ALL codes, staged
        for (int base = 0; base < KSZ; base += 8) {
            for (int r = 0; r < 8; r++) {
                const float4* src = (const float4*)(cb + (long long)(base + r) * DIMD);
                float4* dstp = (float4*)(stg0 + r * 516);
#pragma unroll
                for (int i = 0; i < 4; i++) dstp[lane + i * 32] = src[lane + i * 32];
            }
            __syncwarp();
            if (lane < 8) {
                int k = base + lane;
                const float* crow = stg0 + lane * 516;
                float e = 0.f;
#pragma unroll 8
                for (int d = 0; d < DIMD; d++) e = fmaf(rs[d], crow[d], e);
                float tt = fmaf(-2.f, e, aR);
                float dd = tt + cnm[k];
                if (dd < bd || (dd == bd && k < bk)) { bd = dd; bk = k; }
            }
            __syncwarp();
        }
    }
    // warp reduce lexicographic (min d, then min k)
#pragma unroll
    for (int o = 16; o > 0; o >>= 1) {
        float d2 = __shfl_down_sync(0xffffffffu, bd, o);
        int   k2 = __shfl_down_sync(0xffffffffu, bk, o);
        if (d2 < bd || (d2 == bd && k2 < bk)) { bd = d2; bk = k2; }
    }
    const int bestK = __shfl_sync(0xffffffffu, bk, 0);
    if (lane == 0 && outIdx) outIdx[(long long)row * NQ + level] = (float)bestK;

    // elementwise update: res -= q ; outQ += q ; loss partial
    const float* __restrict__ q = cb + (long long)bestK * DIMD;
    float* oq = outQ + (long long)row * DIMD;
    double ls = 0.0;
    for (int e = lane; e < DIMD; e += 32) {
        float qq = q[e];
        float rv = res[e] - qq;
        res[e] = rv;
        oq[e] += qq;
        ls += (double)rv * rv;
    }
    __syncwarp();
    // exact 16-lane row norm of the new residual
    float S = 0.f;
    if (lane < 16) {
        for (int j = 0; j < 32; j++) { float v = res[16 * j + lane]; S = fmaf(v, v, S); }
    }
    float t1 = S + __shfl_down_sync(0xffffffffu, S, 4);
    float u  = t1 + __shfl_down_sync(0xffffffffu, t1, 8);
    float v2 = u + __shfl_down_sync(0xffffffffu, u, 1);
    float an = v2 + __shfl_down_sync(0xffffffffu, v2, 2);
    if (lane == 0) g_a[row] = an;
#pragma unroll
    for (int o = 16; o > 0; o >>= 1) ls += __shfl_down_sync(0xffffffffu, ls, o);
    if (lane == 0) wpart[wid] = ls;
    __syncthreads();
    if (tid == 0) {
        double t = 0.0;
        for (int w = 0; w < 8; w++) t += wpart[w];
        g_lpart[level * SBLK + blockIdx.x] = t;
    }
}

// ---------------- epilogues ------------------------------------------------
__global__ void rvq_ste(const float* __restrict__ x, float* __restrict__ outQ) {
    int i = blockIdx.x * blockDim.x + threadIdx.x;
    if (i < NROWS * DIMD) {
        float xv = x[i];
        float qv = outQ[i];
        outQ[i] = xv + (qv - xv);
    }
}
__global__ void rvq_finalize(float* __restrict__ outLoss) {
    __shared__ double red[256];
    int tid = threadIdx.x;
    double t = 0.0;
    for (int i = tid; i < NQ * SBLK; i += 256) t += g_lpart[i];
    red[tid] = t; __syncthreads();
    for (int o = 128; o > 0; o >>= 1) {
        if (tid < o) red[tid] += red[tid + o];
        __syncthreads();
    }
    if (tid == 0) {
        double denom = 8.0 * (double)NROWS * (double)DIMD;
        *outLoss = (float)(red[0] * 1.25 / denom);
    }
}

// ---------------------------------------------------------------------------
extern "C" void kernel_launch(void* const* d_in, const int* in_sizes, int n_in,
                              void* d_out, int out_size) {
    const float* x  = (const float*)d_in[0];
    const float* cb = (const float*)d_in[1];
    float* out = (float*)d_out;
    float* outQ = out;
    float* outIdx = (out_size >= NROWS * DIMD + NROWS * NQ) ? (out + NROWS * DIMD)
                                                            : (float*)0;

    cudaFuncSetAttribute(rvq_filter, cudaFuncAttributeMaxDynamicSharedMemorySize,
                         SM_FTOT);
    cudaFuncSetAttribute(rvq_select, cudaFuncAttributeMaxDynamicSharedMemorySize,
                         SEL_TOT);

    rvq_init<<<(NROWS * DIMD / 4 + 255) / 256, 256>>>((const float4*)x, (float4*)outQ);
    rvq_qcode<<<NQ * KSZ / 8, 256>>>(cb);
    rvq_cnorm<<<(NQ * KSZ + 255) / 256, 256>>>(cb);
    rvq_uvmax<<<NQ, 256>>>();
    rvq_norm0<<<(NROWS + 255) / 256, 256>>>();

    for (int l = 0; l < NQ; l++) {
        rvq_qres<<<NROWS / 8, 256>>>();
        rvq_filter<<<NROWS / 128, 256, SM_FTOT>>>(l);
        rvq_select<<<SBLK, 256, SEL_TOT>>>(cb + (long long)l * KSZ * DIMD,
                                           outQ, outIdx, l);
    }

    rvq_ste<<<(NROWS * DIMD + 255) / 256, 256>>>(x, outQ);
    if (out_size >= NROWS * DIMD + NROWS * NQ + 1) {
        rvq_finalize<<<1, 256>>>(out + NROWS * DIMD + NROWS * NQ);
    }
}